// round 4
// baseline (speedup 1.0000x reference)
#include <cuda_runtime.h>

#define BB 8
#define NN 131072
#define PRE 2048
#define POST 512
#define CAP 4096
#define NBINS 4096
#define SCORE_TH 0.1f
#define IOU_TH 0.7f

// ---------------- device scratch (no allocations allowed) ----------------
__device__ float              g_scores[BB * NN];
__device__ int                g_hist[BB * NBINS];
__device__ int                g_cutoff[BB];
__device__ int                g_cnt[BB];
__device__ unsigned long long g_cand[BB * CAP];
__device__ int                g_topi[BB * PRE];
__device__ float              g_tops[BB * PRE];
__device__ int                g_sel[BB * POST];
__device__ float              g_msk[BB * POST];

// ---------------- kernels ----------------
__global__ void k_zero() {
    int t = blockIdx.x * blockDim.x + threadIdx.x;
    if (t < BB * NBINS) g_hist[t] = 0;
    if (t < BB) g_cnt[t] = 0;
}

__device__ __forceinline__ void hist_update(float s, int hbase) {
    if (s >= SCORE_TH) {
        int bin = (int)(s * (float)NBINS);
        bin = bin < 0 ? 0 : (bin > NBINS - 1 ? NBINS - 1 : bin);
        atomicAdd(&g_hist[hbase + bin], 1);
    }
}

// Vectorized: each thread handles 4 boxes (12 floats = 3x float4, 16B-aligned
// since the 48B stride is a multiple of 16).
__global__ void k_score(const float4* __restrict__ cls4) {
    int t = blockIdx.x * blockDim.x + threadIdx.x;
    if (t >= BB * NN / 4) return;
    float4 a = cls4[t * 3 + 0];
    float4 b = cls4[t * 3 + 1];
    float4 c = cls4[t * 3 + 2];
    float s0 = fmaxf(a.x, fmaxf(a.y, a.z));
    float s1 = fmaxf(a.w, fmaxf(b.x, b.y));
    float s2 = fmaxf(b.z, fmaxf(b.w, c.x));
    float s3 = fmaxf(c.y, fmaxf(c.z, c.w));
    reinterpret_cast<float4*>(g_scores)[t] = make_float4(s0, s1, s2, s3);
    int hbase = (t >> 15) * NBINS;  // batch = (4t)/NN = t>>15
    hist_update(s0, hbase);
    hist_update(s1, hbase);
    hist_update(s2, hbase);
    hist_update(s3, hbase);
}

__global__ void k_cutoff() {
    int b = threadIdx.x;
    if (b >= BB) return;
    int acc = 0, c = 0;
    for (int bin = NBINS - 1; bin >= 0; --bin) {
        acc += g_hist[b * NBINS + bin];
        if (acc >= PRE) { c = bin; break; }
    }
    g_cutoff[b] = c;
}

__device__ __forceinline__ void compact_one(float s, int gidx, int b, int cut) {
    if (s < SCORE_TH) return;
    int bin = (int)(s * (float)NBINS);
    bin = bin < 0 ? 0 : (bin > NBINS - 1 ? NBINS - 1 : bin);
    if (bin < cut) return;
    int pos = atomicAdd(&g_cnt[b], 1);
    if (pos < CAP) {
        // key: score bits high (positive floats order like uints),
        // ~local_index low so ties prefer the LOWER index (jax top_k rule).
        unsigned lo = ~(unsigned)(gidx & (NN - 1));
        g_cand[b * CAP + pos] =
            ((unsigned long long)__float_as_uint(s) << 32) | (unsigned long long)lo;
    }
}

__global__ void k_compact() {
    int t = blockIdx.x * blockDim.x + threadIdx.x;
    if (t >= BB * NN / 4) return;
    float4 s4 = reinterpret_cast<const float4*>(g_scores)[t];
    int b = t >> 15;
    int cut = g_cutoff[b];
    int gi = t * 4;
    compact_one(s4.x, gi + 0, b, cut);
    compact_one(s4.y, gi + 1, b, cut);
    compact_one(s4.z, gi + 2, b, cut);
    compact_one(s4.w, gi + 3, b, cut);
}

__global__ void k_sort() {
    __shared__ unsigned long long sh[CAP];
    int b = blockIdx.x;
    int cnt = g_cnt[b];
    if (cnt > CAP) cnt = CAP;
    for (int i = threadIdx.x; i < CAP; i += blockDim.x)
        sh[i] = (i < cnt) ? g_cand[b * CAP + i] : 0ULL;
    __syncthreads();
    // bitonic sort, descending
    for (int k = 2; k <= CAP; k <<= 1) {
        for (int j = k >> 1; j > 0; j >>= 1) {
            for (int i = threadIdx.x; i < CAP; i += blockDim.x) {
                int l = i ^ j;
                if (l > i) {
                    unsigned long long a = sh[i], c = sh[l];
                    bool sw = ((i & k) == 0) ? (a < c) : (a > c);
                    if (sw) { sh[i] = c; sh[l] = a; }
                }
            }
            __syncthreads();
        }
    }
    for (int r = threadIdx.x; r < PRE; r += blockDim.x) {
        unsigned long long key = sh[r];
        float s = __uint_as_float((unsigned)(key >> 32));
        int idx = (int)(~(unsigned)key);
        if (s < SCORE_TH) idx = 0;  // padding entry, never kept, safe index
        g_tops[b * PRE + r] = s;
        g_topi[b * PRE + r] = idx;
    }
}

// Fused greedy NMS: geometry + removed state live in shared memory; suppression
// for a kept box i is computed on the fly (no 2048x2048 mask matrix).
// All arithmetic uses explicit round-to-nearest intrinsics so ptxas cannot
// FMA-contract and diverge from the reference's unfused op-by-op rounding.
__global__ void k_nms(const float* __restrict__ boxes_tea) {
    __shared__ float sx1[PRE], sx2[PRE], sy1[PRE], sy2[PRE], sar[PRE];
    __shared__ unsigned char srem[PRE];
    int b = blockIdx.x;
    for (int i = threadIdx.x; i < PRE; i += blockDim.x) {
        int idx = g_topi[b * PRE + i];
        const float* bp = boxes_tea + ((size_t)b * NN + idx) * 7;
        float x = bp[0], y = bp[1], dx = bp[3], dy = bp[4];
        float hx = __fmul_rn(0.5f, dx);
        float hy = __fmul_rn(0.5f, dy);
        sx1[i] = __fsub_rn(x, hx);
        sx2[i] = __fadd_rn(x, hx);
        sy1[i] = __fsub_rn(y, hy);
        sy2[i] = __fadd_rn(y, hy);
        sar[i] = __fmul_rn(dx, dy);
        srem[i] = (g_tops[b * PRE + i] < SCORE_TH) ? (unsigned char)1 : (unsigned char)0;
    }
    __syncthreads();
    int cnt = 0;
    for (int i = 0; i < PRE; i++) {
        if (cnt >= POST) break;       // uniform
        if (srem[i]) continue;        // uniform (all threads read same byte)
        float x1 = sx1[i], x2 = sx2[i], y1 = sy1[i], y2 = sy2[i], ar = sar[i];
#pragma unroll
        for (int q = 0; q < PRE / 512; q++) {
            int j = threadIdx.x + q * 512;
            if (j > i) {
                float iw = fmaxf(__fsub_rn(fminf(x2, sx2[j]), fmaxf(x1, sx1[j])), 0.0f);
                float ih = fmaxf(__fsub_rn(fminf(y2, sy2[j]), fmaxf(y1, sy1[j])), 0.0f);
                float inter = __fmul_rn(iw, ih);
                float denom = fmaxf(__fsub_rn(__fadd_rn(ar, sar[j]), inter), 1e-6f);
                float iou = __fdiv_rn(inter, denom);
                if (iou > IOU_TH) srem[j] = 1;
            }
        }
        if (threadIdx.x == 0) {
            g_sel[b * POST + cnt] = g_topi[b * PRE + i];
            g_msk[b * POST + cnt] = 1.0f;
        }
        cnt++;
        __syncthreads();
    }
    for (int r = cnt + threadIdx.x; r < POST; r += blockDim.x) {
        g_sel[b * POST + r] = 0;
        g_msk[b * POST + r] = 0.0f;
    }
}

// Output layout (flattened, float32, reference return order):
//  O0 cls_kd_stu  (4096)      O1 cls_kd_tea (4096)
//  O2 rois_tea    (8*512*7)   O3 roi_scores_tea (4096)  O4 roi_labels_tea (4096)
//  O5 rois_stu    (8*512*7)   O6 roi_scores_stu (4096)  O7 roi_labels_stu (4096)
//  O8 cls_select  (8*512*3)   O9 select_mask (4096)
__global__ void k_gather(const float* __restrict__ box_tea,
                         const float* __restrict__ cls_tea,
                         const float* __restrict__ box_stu,
                         const float* __restrict__ cls_stu,
                         const float* __restrict__ cls_preds,
                         const float* __restrict__ rcnn,
                         float* __restrict__ out) {
    int t = blockIdx.x * blockDim.x + threadIdx.x;
    if (t >= BB * POST) return;
    const int O0 = 0, O1 = 4096, O2 = 8192, O3 = 36864, O4 = 40960;
    const int O5 = 45056, O6 = 73728, O7 = 77824, O8 = 81920, O9 = 94208;
    float m = g_msk[t];
    int idx = g_sel[t];
    int b = t / POST;
    size_t base = (size_t)b * NN + (size_t)idx;

    const float* ct = cls_tea + base * 3;
    float a0 = ct[0], a1 = ct[1], a2 = ct[2];
    float sT = a0;
    int lT = 0;
    if (a1 > sT) { sT = a1; lT = 1; }
    if (a2 > sT) { sT = a2; lT = 2; }

    const float* cs = cls_stu + base * 3;
    float b0 = cs[0], b1 = cs[1], b2 = cs[2];
    float sS = b0;
    int lS = 0;
    if (b1 > sS) { sS = b1; lS = 1; }
    if (b2 > sS) { sS = b2; lS = 2; }

    const float* pt = box_tea + base * 7;
    const float* ps = box_stu + base * 7;
    const float* pc = cls_preds + base * 3;
    float p0 = __fmul_rn(pc[0], m), p1 = __fmul_rn(pc[1], m), p2 = __fmul_rn(pc[2], m);

    out[O0 + t] = __fmul_rn(fmaxf(p0, fmaxf(p1, p2)), m);
    out[O1 + t] = __fmul_rn(rcnn[t], m);
#pragma unroll
    for (int j = 0; j < 7; j++) {
        out[O2 + t * 7 + j] = __fmul_rn(pt[j], m);
        out[O5 + t * 7 + j] = __fmul_rn(ps[j], m);
    }
    out[O3 + t] = __fmul_rn(sT, m);
    out[O4 + t] = (m > 0.0f) ? (float)(lT + 1) : 1.0f;
    out[O6 + t] = __fmul_rn(sS, m);
    out[O7 + t] = (m > 0.0f) ? (float)(lS + 1) : 1.0f;
    out[O8 + t * 3 + 0] = p0;
    out[O8 + t * 3 + 1] = p1;
    out[O8 + t * 3 + 2] = p2;
    out[O9 + t] = m;
}

extern "C" void kernel_launch(void* const* d_in, const int* in_sizes, int n_in,
                              void* d_out, int out_size) {
    const float* box_tea   = (const float*)d_in[0];
    const float* cls_tea   = (const float*)d_in[1];
    const float* box_stu   = (const float*)d_in[2];
    const float* cls_stu   = (const float*)d_in[3];
    const float* cls_preds = (const float*)d_in[4];
    const float* rcnn      = (const float*)d_in[5];
    float* out = (float*)d_out;

    k_zero<<<(BB * NBINS + 255) / 256, 256>>>();
    k_score<<<(BB * NN / 4) / 256, 256>>>((const float4*)cls_tea);
    k_cutoff<<<1, 32>>>();
    k_compact<<<(BB * NN / 4) / 256, 256>>>();
    k_sort<<<BB, 1024>>>();
    k_nms<<<BB, 512>>>(box_tea);
    k_gather<<<(BB * POST + 127) / 128, 128>>>(box_tea, cls_tea, box_stu, cls_stu,
                                               cls_preds, rcnn, out);
}

// round 5
// speedup vs baseline: 3.0180x; 3.0180x over previous
#include <cuda_runtime.h>

#define BB 8
#define NN 131072
#define PRE 2048
#define POST 512
#define CAP 4096
#define NBINS 4096
#define SCORE_TH 0.1f
#define IOU_TH 0.7f
#define PD 8  // cp.async prefetch depth in k_scan (power of 2)

// ---------------- device scratch (no allocations allowed) ----------------
__device__ float              g_scores[BB * NN];
__device__ int                g_hist[BB * NBINS];
__device__ int                g_cutoff[BB];
__device__ int                g_cnt[BB];
__device__ unsigned long long g_cand[BB * CAP];
__device__ int                g_topi[BB * PRE];
__device__ float              g_tops[BB * PRE];
__device__ int                g_sel[BB * POST];
__device__ float              g_msk[BB * POST];
// NMS geometry (SoA) and suppression bit-matrix: 32 u64 words per row (2048 bits)
__device__ float              g_gx1[BB * PRE], g_gx2[BB * PRE];
__device__ float              g_gy1[BB * PRE], g_gy2[BB * PRE];
__device__ float              g_gar[BB * PRE];
__device__ unsigned long long g_mask[BB * PRE * 32];

// ---------------- kernels ----------------
__global__ void k_zero() {
    int t = blockIdx.x * blockDim.x + threadIdx.x;
    if (t < BB * NBINS) g_hist[t] = 0;
    if (t < BB) g_cnt[t] = 0;
}

__device__ __forceinline__ void hist_update(float s, int hbase) {
    if (s >= SCORE_TH) {
        int bin = (int)(s * (float)NBINS);
        bin = bin < 0 ? 0 : (bin > NBINS - 1 ? NBINS - 1 : bin);
        atomicAdd(&g_hist[hbase + bin], 1);
    }
}

// Vectorized: each thread handles 4 boxes (12 floats = 3x float4).
__global__ void k_score(const float4* __restrict__ cls4) {
    int t = blockIdx.x * blockDim.x + threadIdx.x;
    if (t >= BB * NN / 4) return;
    float4 a = cls4[t * 3 + 0];
    float4 b = cls4[t * 3 + 1];
    float4 c = cls4[t * 3 + 2];
    float s0 = fmaxf(a.x, fmaxf(a.y, a.z));
    float s1 = fmaxf(a.w, fmaxf(b.x, b.y));
    float s2 = fmaxf(b.z, fmaxf(b.w, c.x));
    float s3 = fmaxf(c.y, fmaxf(c.z, c.w));
    reinterpret_cast<float4*>(g_scores)[t] = make_float4(s0, s1, s2, s3);
    int hbase = (t >> 15) * NBINS;
    hist_update(s0, hbase);
    hist_update(s1, hbase);
    hist_update(s2, hbase);
    hist_update(s3, hbase);
}

__global__ void k_cutoff() {
    int b = threadIdx.x;
    if (b >= BB) return;
    int acc = 0, c = 0;
    for (int bin = NBINS - 1; bin >= 0; --bin) {
        acc += g_hist[b * NBINS + bin];
        if (acc >= PRE) { c = bin; break; }
    }
    g_cutoff[b] = c;
}

__device__ __forceinline__ void compact_one(float s, int gidx, int b, int cut) {
    if (s < SCORE_TH) return;
    int bin = (int)(s * (float)NBINS);
    bin = bin < 0 ? 0 : (bin > NBINS - 1 ? NBINS - 1 : bin);
    if (bin < cut) return;
    int pos = atomicAdd(&g_cnt[b], 1);
    if (pos < CAP) {
        unsigned lo = ~(unsigned)(gidx & (NN - 1));
        g_cand[b * CAP + pos] =
            ((unsigned long long)__float_as_uint(s) << 32) | (unsigned long long)lo;
    }
}

__global__ void k_compact() {
    int t = blockIdx.x * blockDim.x + threadIdx.x;
    if (t >= BB * NN / 4) return;
    float4 s4 = reinterpret_cast<const float4*>(g_scores)[t];
    int b = t >> 15;
    int cut = g_cutoff[b];
    int gi = t * 4;
    compact_one(s4.x, gi + 0, b, cut);
    compact_one(s4.y, gi + 1, b, cut);
    compact_one(s4.z, gi + 2, b, cut);
    compact_one(s4.w, gi + 3, b, cut);
}

__global__ void k_sort() {
    __shared__ unsigned long long sh[CAP];
    int b = blockIdx.x;
    int cnt = g_cnt[b];
    if (cnt > CAP) cnt = CAP;
    for (int i = threadIdx.x; i < CAP; i += blockDim.x)
        sh[i] = (i < cnt) ? g_cand[b * CAP + i] : 0ULL;
    __syncthreads();
    for (int k = 2; k <= CAP; k <<= 1) {
        for (int j = k >> 1; j > 0; j >>= 1) {
            for (int i = threadIdx.x; i < CAP; i += blockDim.x) {
                int l = i ^ j;
                if (l > i) {
                    unsigned long long a = sh[i], c = sh[l];
                    bool sw = ((i & k) == 0) ? (a < c) : (a > c);
                    if (sw) { sh[i] = c; sh[l] = a; }
                }
            }
            __syncthreads();
        }
    }
    for (int r = threadIdx.x; r < PRE; r += blockDim.x) {
        unsigned long long key = sh[r];
        float s = __uint_as_float((unsigned)(key >> 32));
        int idx = (int)(~(unsigned)key);
        if (s < SCORE_TH) idx = 0;
        g_tops[b * PRE + r] = s;
        g_topi[b * PRE + r] = idx;
    }
}

// Precompute candidate geometry SoA (same _rn rounding as the reference).
__global__ void k_geom(const float* __restrict__ boxes_tea) {
    int t = blockIdx.x * blockDim.x + threadIdx.x;
    if (t >= BB * PRE) return;
    int b = t / PRE;
    int idx = g_topi[t];
    const float* bp = boxes_tea + ((size_t)b * NN + idx) * 7;
    float x = bp[0], y = bp[1], dx = bp[3], dy = bp[4];
    float hx = __fmul_rn(0.5f, dx);
    float hy = __fmul_rn(0.5f, dy);
    g_gx1[t] = __fsub_rn(x, hx);
    g_gx2[t] = __fadd_rn(x, hx);
    g_gy1[t] = __fsub_rn(y, hy);
    g_gy2[t] = __fadd_rn(y, hy);
    g_gar[t] = __fmul_rn(dx, dy);
}

// Suppression bit matrix, chip-parallel. Block = 64 threads handles a
// (64-row x 64-col) tile; thread tid computes one u64 word for row
// by*64+tid covering columns bx*64..bx*64+63. bit k set iff j>i && iou>0.7.
__global__ void k_mask() {
    __shared__ float cx1[64], cx2[64], cy1[64], cy2[64], car[64];
    int bx = blockIdx.x, by = blockIdx.y, b = blockIdx.z;
    int tid = threadIdx.x;
    int i = by * 64 + tid;
    int base = b * PRE;
    unsigned long long* dst = &g_mask[(size_t)(base + i) * 32 + bx];
    if (bx < by) {  // all j < i: word is zero
        *dst = 0ULL;
        return;
    }
    int c = bx * 64 + tid;
    cx1[tid] = g_gx1[base + c];
    cx2[tid] = g_gx2[base + c];
    cy1[tid] = g_gy1[base + c];
    cy2[tid] = g_gy2[base + c];
    car[tid] = g_gar[base + c];
    __syncthreads();
    float x1 = g_gx1[base + i], x2 = g_gx2[base + i];
    float y1 = g_gy1[base + i], y2 = g_gy2[base + i];
    float ar = g_gar[base + i];
    unsigned long long word = 0ULL;
#pragma unroll 16
    for (int k = 0; k < 64; k++) {
        int j = bx * 64 + k;
        float iw = fmaxf(__fsub_rn(fminf(x2, cx2[k]), fmaxf(x1, cx1[k])), 0.0f);
        float ih = fmaxf(__fsub_rn(fminf(y2, cy2[k]), fmaxf(y1, cy1[k])), 0.0f);
        float inter = __fmul_rn(iw, ih);
        float denom = fmaxf(__fsub_rn(__fadd_rn(ar, car[k]), inter), 1e-6f);
        float iou = __fdiv_rn(inter, denom);
        if ((j > i) && (iou > IOU_TH)) word |= (1ULL << k);
    }
    *dst = word;
}

__device__ __forceinline__ void cp_async8(void* smem_dst, const void* gmem_src) {
    unsigned d = (unsigned)__cvta_generic_to_shared(smem_dst);
    asm volatile("cp.async.ca.shared.global [%0], [%1], 8;" ::"r"(d), "l"(gmem_src));
}
__device__ __forceinline__ void cp_commit() {
    asm volatile("cp.async.commit_group;");
}
__device__ __forceinline__ void cp_wait_back() {  // allow PD-1 pending
    asm volatile("cp.async.wait_group 7;");
}
__device__ __forceinline__ void cp_wait_all() {
    asm volatile("cp.async.wait_group 0;");
}

// Serial greedy scan: 1 warp per batch. Lane w owns u64 word w of the
// 2048-bit suppression accumulator. Mask rows prefetched via cp.async ring.
__global__ void k_scan() {
    __shared__ unsigned long long ring[PD][32];
    int b = blockIdx.x;
    int lane = threadIdx.x;
    const unsigned long long* rowbase = g_mask + (size_t)b * PRE * 32;

    // Pre-seed accumulator with invalid rows (score below threshold).
    unsigned long long acc = 0ULL;
    for (int k = 0; k < 64; k++) {
        float s = g_tops[b * PRE + lane * 64 + k];
        if (s < SCORE_TH) acc |= (1ULL << k);
    }

    // Prologue: prefetch first PD rows.
    for (int p = 0; p < PD; p++) {
        cp_async8(&ring[p][lane], rowbase + (size_t)p * 32 + lane);
        cp_commit();
    }

    int cnt = 0;
    for (int i = 0; i < PRE; i++) {
        cp_wait_back();  // row i (oldest group) has landed
        unsigned long long w = __shfl_sync(0xffffffffu, acc, i >> 6);
        bool keep = !((w >> (i & 63)) & 1ULL);
        int slot = i & (PD - 1);
        if (keep) {
            if (lane == 0) {
                g_sel[b * POST + cnt] = g_topi[b * PRE + i];
                g_msk[b * POST + cnt] = 1.0f;
            }
            acc |= ring[slot][lane];
            cnt++;
            if (cnt >= POST) break;
        }
        int nr = i + PD;
        if (nr > PRE - 1) nr = PRE - 1;  // clamped duplicate, harmless
        cp_async8(&ring[slot][lane], rowbase + (size_t)nr * 32 + lane);
        cp_commit();
    }
    cp_wait_all();  // drain before exit
    for (int r = cnt + lane; r < POST; r += 32) {
        g_sel[b * POST + r] = 0;
        g_msk[b * POST + r] = 0.0f;
    }
}

// Output layout (flattened, float32, reference return order):
//  O0 cls_kd_stu  (4096)      O1 cls_kd_tea (4096)
//  O2 rois_tea    (8*512*7)   O3 roi_scores_tea (4096)  O4 roi_labels_tea (4096)
//  O5 rois_stu    (8*512*7)   O6 roi_scores_stu (4096)  O7 roi_labels_stu (4096)
//  O8 cls_select  (8*512*3)   O9 select_mask (4096)
__global__ void k_gather(const float* __restrict__ box_tea,
                         const float* __restrict__ cls_tea,
                         const float* __restrict__ box_stu,
                         const float* __restrict__ cls_stu,
                         const float* __restrict__ cls_preds,
                         const float* __restrict__ rcnn,
                         float* __restrict__ out) {
    int t = blockIdx.x * blockDim.x + threadIdx.x;
    if (t >= BB * POST) return;
    const int O0 = 0, O1 = 4096, O2 = 8192, O3 = 36864, O4 = 40960;
    const int O5 = 45056, O6 = 73728, O7 = 77824, O8 = 81920, O9 = 94208;
    float m = g_msk[t];
    int idx = g_sel[t];
    int b = t / POST;
    size_t base = (size_t)b * NN + (size_t)idx;

    const float* ct = cls_tea + base * 3;
    float a0 = ct[0], a1 = ct[1], a2 = ct[2];
    float sT = a0;
    int lT = 0;
    if (a1 > sT) { sT = a1; lT = 1; }
    if (a2 > sT) { sT = a2; lT = 2; }

    const float* cs = cls_stu + base * 3;
    float b0 = cs[0], b1 = cs[1], b2 = cs[2];
    float sS = b0;
    int lS = 0;
    if (b1 > sS) { sS = b1; lS = 1; }
    if (b2 > sS) { sS = b2; lS = 2; }

    const float* pt = box_tea + base * 7;
    const float* ps = box_stu + base * 7;
    const float* pc = cls_preds + base * 3;
    float p0 = __fmul_rn(pc[0], m), p1 = __fmul_rn(pc[1], m), p2 = __fmul_rn(pc[2], m);

    out[O0 + t] = __fmul_rn(fmaxf(p0, fmaxf(p1, p2)), m);
    out[O1 + t] = __fmul_rn(rcnn[t], m);
#pragma unroll
    for (int j = 0; j < 7; j++) {
        out[O2 + t * 7 + j] = __fmul_rn(pt[j], m);
        out[O5 + t * 7 + j] = __fmul_rn(ps[j], m);
    }
    out[O3 + t] = __fmul_rn(sT, m);
    out[O4 + t] = (m > 0.0f) ? (float)(lT + 1) : 1.0f;
    out[O6 + t] = __fmul_rn(sS, m);
    out[O7 + t] = (m > 0.0f) ? (float)(lS + 1) : 1.0f;
    out[O8 + t * 3 + 0] = p0;
    out[O8 + t * 3 + 1] = p1;
    out[O8 + t * 3 + 2] = p2;
    out[O9 + t] = m;
}

extern "C" void kernel_launch(void* const* d_in, const int* in_sizes, int n_in,
                              void* d_out, int out_size) {
    const float* box_tea   = (const float*)d_in[0];
    const float* cls_tea   = (const float*)d_in[1];
    const float* box_stu   = (const float*)d_in[2];
    const float* cls_stu   = (const float*)d_in[3];
    const float* cls_preds = (const float*)d_in[4];
    const float* rcnn      = (const float*)d_in[5];
    float* out = (float*)d_out;

    k_zero<<<(BB * NBINS + 255) / 256, 256>>>();
    k_score<<<(BB * NN / 4) / 256, 256>>>((const float4*)cls_tea);
    k_cutoff<<<1, 32>>>();
    k_compact<<<(BB * NN / 4) / 256, 256>>>();
    k_sort<<<BB, 1024>>>();
    k_geom<<<(BB * PRE) / 256, 256>>>(box_tea);
    k_mask<<<dim3(32, 32, BB), 64>>>();
    k_scan<<<BB, 32>>>();
    k_gather<<<(BB * POST + 127) / 128, 128>>>(box_tea, cls_tea, box_stu, cls_stu,
                                               cls_preds, rcnn, out);
}

// round 9
// speedup vs baseline: 3.0679x; 1.0165x over previous
#include <cuda_runtime.h>

#define BB 8
#define NN 131072
#define PRE 2048
#define POST 512
#define CAP 4096
#define NBINS 4096
#define SCORE_TH 0.1f
#define IOU_TH 0.7f
#define PD 8  // cp.async prefetch depth in k_scan (power of 2)

// ---------------- device scratch (no allocations allowed) ----------------
__device__ float              g_scores[BB * NN];
__device__ int                g_hist[BB * NBINS];
__device__ int                g_cutoff[BB];
__device__ int                g_cnt[BB];
__device__ int                g_ticket;
__device__ unsigned long long g_cand[BB * CAP];
__device__ int                g_topi[BB * PRE];
__device__ float              g_tops[BB * PRE];
__device__ int                g_sel[BB * POST];
__device__ float              g_msk[BB * POST];
__device__ float              g_gx1[BB * PRE], g_gx2[BB * PRE];
__device__ float              g_gy1[BB * PRE], g_gy2[BB * PRE];
__device__ float              g_gar[BB * PRE];
__device__ unsigned long long g_mask[BB * PRE * 32];

// ---------------- kernels ----------------
__global__ void k_zero() {
    int t = blockIdx.x * blockDim.x + threadIdx.x;
    if (t < BB * NBINS) g_hist[t] = 0;
    if (t < BB) g_cnt[t] = 0;
    if (t == 0) g_ticket = 0;
}

__device__ __forceinline__ void hist_update(float s, int hbase) {
    if (s >= SCORE_TH) {
        int bin = (int)(s * (float)NBINS);
        bin = bin < 0 ? 0 : (bin > NBINS - 1 ? NBINS - 1 : bin);
        atomicAdd(&g_hist[hbase + bin], 1);
    }
}

// 8 boxes/thread (6x LDG.128, MLP=6). Fused cutoff via last-block pattern.
__global__ void k_score(const float4* __restrict__ cls4) {
    int t = blockIdx.x * blockDim.x + threadIdx.x;  // exactly BB*NN/8 threads
    float4 q[6];
#pragma unroll
    for (int u = 0; u < 6; u++) q[u] = cls4[t * 6 + u];
    float s[8];
    s[0] = fmaxf(q[0].x, fmaxf(q[0].y, q[0].z));
    s[1] = fmaxf(q[0].w, fmaxf(q[1].x, q[1].y));
    s[2] = fmaxf(q[1].z, fmaxf(q[1].w, q[2].x));
    s[3] = fmaxf(q[2].y, fmaxf(q[2].z, q[2].w));
    s[4] = fmaxf(q[3].x, fmaxf(q[3].y, q[3].z));
    s[5] = fmaxf(q[3].w, fmaxf(q[4].x, q[4].y));
    s[6] = fmaxf(q[4].z, fmaxf(q[4].w, q[5].x));
    s[7] = fmaxf(q[5].y, fmaxf(q[5].z, q[5].w));
    float4* so = reinterpret_cast<float4*>(g_scores);
    so[t * 2 + 0] = make_float4(s[0], s[1], s[2], s[3]);
    so[t * 2 + 1] = make_float4(s[4], s[5], s[6], s[7]);
    int hbase = (t >> 14) * NBINS;  // batch = 8t/NN = t>>14
#pragma unroll
    for (int u = 0; u < 8; u++) hist_update(s[u], hbase);

    // ---- fused cutoff: last block computes all 8 batches ----
    __threadfence();
    __shared__ int isLast;
    if (threadIdx.x == 0) isLast = (atomicAdd(&g_ticket, 1) == (int)gridDim.x - 1);
    __syncthreads();
    if (isLast && threadIdx.x < 256) {
        int b = threadIdx.x >> 5;
        int lane = threadIdx.x & 31;
        // lane covers 128 bins; lane 0 = topmost chunk
        int hi = NBINS - 128 * lane;
        int lo = hi - 128;
        int sum = 0;
        for (int bin = lo; bin < hi; bin++) sum += g_hist[b * NBINS + bin];
        int incl = sum;
        for (int o = 1; o < 32; o <<= 1) {
            int n = __shfl_up_sync(0xffffffffu, incl, o);
            if (lane >= o) incl += n;
        }
        int excl = incl - sum;
        unsigned ball = __ballot_sync(0xffffffffu, incl >= PRE);
        if (ball) {
            int sel = __ffs(ball) - 1;
            if (lane == sel) {
                int acc = excl, bin;
                for (bin = hi - 1; bin >= lo; bin--) {
                    acc += g_hist[b * NBINS + bin];
                    if (acc >= PRE) break;
                }
                g_cutoff[b] = bin;
            }
        } else if (lane == 0) {
            g_cutoff[b] = 0;
        }
    }
}

__device__ __forceinline__ void compact_one(float s, int gidx, int b, int cut) {
    if (s < SCORE_TH) return;
    int bin = (int)(s * (float)NBINS);
    bin = bin < 0 ? 0 : (bin > NBINS - 1 ? NBINS - 1 : bin);
    if (bin < cut) return;
    int pos = atomicAdd(&g_cnt[b], 1);
    if (pos < CAP) {
        // score bits high; ~local_index low -> ties prefer LOWER index (jax rule)
        unsigned lo = ~(unsigned)(gidx & (NN - 1));
        g_cand[b * CAP + pos] =
            ((unsigned long long)__float_as_uint(s) << 32) | (unsigned long long)lo;
    }
}

// 16 scores/thread (4x LDG.128, MLP=4)
__global__ void k_compact() {
    int t = blockIdx.x * blockDim.x + threadIdx.x;  // exactly BB*NN/16 threads
    const float4* sp = reinterpret_cast<const float4*>(g_scores);
    float4 f[4];
#pragma unroll
    for (int u = 0; u < 4; u++) f[u] = sp[t * 4 + u];
    int b = t >> 13;  // 16t/NN
    int cut = g_cutoff[b];
    int gi = t * 16;
#pragma unroll
    for (int u = 0; u < 4; u++) {
        compact_one(f[u].x, gi + u * 4 + 0, b, cut);
        compact_one(f[u].y, gi + u * 4 + 1, b, cut);
        compact_one(f[u].z, gi + u * 4 + 2, b, cut);
        compact_one(f[u].w, gi + u * 4 + 3, b, cut);
    }
}

// Hybrid bitonic sort (descending), 4096 elems, 1024 threads x 4 regs.
// Element i = 4*t+s. Passes: j>=128 via smem, j=4..64 via shfl, j<=2 in regs.
// Same compare-exchange rule as the proven smem version. Tail emits topi/tops
// and the NMS geometry SoA (k_geom folded in).
__global__ void k_sort(const float* __restrict__ boxes_tea) {
    __shared__ unsigned long long sh[CAP];
    int b = blockIdx.x;
    int t = threadIdx.x;
    int cnt = g_cnt[b];
    if (cnt > CAP) cnt = CAP;
    unsigned long long v[4];
#pragma unroll
    for (int s = 0; s < 4; s++) {
        int i = 4 * t + s;
        v[s] = (i < cnt) ? g_cand[b * CAP + i] : 0ULL;
    }
    for (int k = 2; k <= CAP; k <<= 1) {
        for (int j = k >> 1; j >= 128; j >>= 1) {  // smem passes
#pragma unroll
            for (int s = 0; s < 4; s++) sh[4 * t + s] = v[s];
            __syncthreads();
#pragma unroll
            for (int s = 0; s < 4; s++) {
                int i = 4 * t + s;
                unsigned long long p = sh[i ^ j];
                bool dir = ((i & k) == 0);
                bool low = ((i & j) == 0);
                bool keepMax = (dir == low);
                unsigned long long mx = v[s] > p ? v[s] : p;
                unsigned long long mn = v[s] > p ? p : v[s];
                v[s] = keepMax ? mx : mn;
            }
            __syncthreads();
        }
        int jhi = (k >> 1) < 64 ? (k >> 1) : 64;
        for (int j = jhi; j >= 4; j >>= 1) {  // shfl passes
            int jt = j >> 2;
#pragma unroll
            for (int s = 0; s < 4; s++) {
                unsigned long long p = __shfl_xor_sync(0xffffffffu, v[s], jt);
                int i = 4 * t + s;
                bool dir = ((i & k) == 0);
                bool low = ((t & jt) == 0);
                bool keepMax = (dir == low);
                unsigned long long mx = v[s] > p ? v[s] : p;
                unsigned long long mn = v[s] > p ? p : v[s];
                v[s] = keepMax ? mx : mn;
            }
        }
        if (k >= 4) {  // reg pass j=2
#pragma unroll
            for (int s = 0; s < 2; s++) {
                int i = 4 * t + s;
                bool dir = ((i & k) == 0);
                unsigned long long a = v[s], c2 = v[s + 2];
                bool sw = dir ? (a < c2) : (a > c2);
                if (sw) { v[s] = c2; v[s + 2] = a; }
            }
        }
        {  // reg pass j=1
#pragma unroll
            for (int s = 0; s < 4; s += 2) {
                int i = 4 * t + s;
                bool dir = ((i & k) == 0);
                unsigned long long a = v[s], c2 = v[s + 1];
                bool sw = dir ? (a < c2) : (a > c2);
                if (sw) { v[s] = c2; v[s + 1] = a; }
            }
        }
    }
#pragma unroll
    for (int s = 0; s < 4; s++) sh[4 * t + s] = v[s];
    __syncthreads();
    for (int r = t; r < PRE; r += 1024) {
        unsigned long long key = sh[r];
        float sc = __uint_as_float((unsigned)(key >> 32));
        int idx = (int)(~(unsigned)key);
        if (sc < SCORE_TH) idx = 0;  // padding: never kept, safe index
        g_tops[b * PRE + r] = sc;
        g_topi[b * PRE + r] = idx;
        const float* bp = boxes_tea + ((size_t)b * NN + idx) * 7;
        float x = bp[0], y = bp[1], dx = bp[3], dy = bp[4];
        float hx = __fmul_rn(0.5f, dx), hy = __fmul_rn(0.5f, dy);
        int g = b * PRE + r;
        g_gx1[g] = __fsub_rn(x, hx);
        g_gx2[g] = __fadd_rn(x, hx);
        g_gy1[g] = __fsub_rn(y, hy);
        g_gy2[g] = __fadd_rn(y, hy);
        g_gar[g] = __fmul_rn(dx, dy);
    }
}

// Suppression bit matrix, chip-parallel. Lower-triangle words are never read
// by k_scan (it masks lanes < i>>6), so bx<by blocks skip entirely.
__global__ void k_mask() {
    __shared__ float cx1[64], cx2[64], cy1[64], cy2[64], car[64];
    int bx = blockIdx.x, by = blockIdx.y, b = blockIdx.z;
    if (bx < by) return;
    int tid = threadIdx.x;
    int i = by * 64 + tid;
    int base = b * PRE;
    int c = bx * 64 + tid;
    cx1[tid] = g_gx1[base + c];
    cx2[tid] = g_gx2[base + c];
    cy1[tid] = g_gy1[base + c];
    cy2[tid] = g_gy2[base + c];
    car[tid] = g_gar[base + c];
    __syncthreads();
    float x1 = g_gx1[base + i], x2 = g_gx2[base + i];
    float y1 = g_gy1[base + i], y2 = g_gy2[base + i];
    float ar = g_gar[base + i];
    unsigned long long word = 0ULL;
#pragma unroll 16
    for (int k = 0; k < 64; k++) {
        int j = bx * 64 + k;
        float iw = fmaxf(__fsub_rn(fminf(x2, cx2[k]), fmaxf(x1, cx1[k])), 0.0f);
        float ih = fmaxf(__fsub_rn(fminf(y2, cy2[k]), fmaxf(y1, cy1[k])), 0.0f);
        float inter = __fmul_rn(iw, ih);
        float denom = fmaxf(__fsub_rn(__fadd_rn(ar, car[k]), inter), 1e-6f);
        float iou = __fdiv_rn(inter, denom);
        if ((j > i) && (iou > IOU_TH)) word |= (1ULL << k);
    }
    g_mask[(size_t)(base + i) * 32 + bx] = word;
}

__device__ __forceinline__ void cp_async8(void* smem_dst, const void* gmem_src) {
    unsigned d = (unsigned)__cvta_generic_to_shared(smem_dst);
    asm volatile("cp.async.ca.shared.global [%0], [%1], 8;" ::"r"(d), "l"(gmem_src));
}
__device__ __forceinline__ void cp_commit() { asm volatile("cp.async.commit_group;"); }
__device__ __forceinline__ void cp_wait_back() { asm volatile("cp.async.wait_group 7;"); }
__device__ __forceinline__ void cp_wait_all() { asm volatile("cp.async.wait_group 0;"); }

// Serial greedy scan: 1 warp per batch; lane owns one u64 of the 2048-bit
// suppression accumulator; mask rows prefetched via cp.async ring.
__global__ void k_scan() {
    __shared__ unsigned long long ring[PD][32];
    int b = blockIdx.x;
    int lane = threadIdx.x;
    const unsigned long long* rowbase = g_mask + (size_t)b * PRE * 32;

    unsigned long long acc = 0ULL;  // pre-seed invalid rows
    for (int k = 0; k < 64; k++) {
        float s = g_tops[b * PRE + lane * 64 + k];
        if (s < SCORE_TH) acc |= (1ULL << k);
    }
    for (int p = 0; p < PD; p++) {
        cp_async8(&ring[p][lane], rowbase + (size_t)p * 32 + lane);
        cp_commit();
    }
    int cnt = 0;
    for (int i = 0; i < PRE; i++) {
        cp_wait_back();
        unsigned long long w = __shfl_sync(0xffffffffu, acc, i >> 6);
        bool keep = !((w >> (i & 63)) & 1ULL);
        int slot = i & (PD - 1);
        if (keep) {
            if (lane == 0) {
                g_sel[b * POST + cnt] = g_topi[b * PRE + i];
                g_msk[b * POST + cnt] = 1.0f;
            }
            if (lane >= (i >> 6)) acc |= ring[slot][lane];
            cnt++;
            if (cnt >= POST) break;
        }
        int nr = i + PD;
        if (nr > PRE - 1) nr = PRE - 1;
        cp_async8(&ring[slot][lane], rowbase + (size_t)nr * 32 + lane);
        cp_commit();
    }
    cp_wait_all();
    for (int r = cnt + lane; r < POST; r += 32) {
        g_sel[b * POST + r] = 0;
        g_msk[b * POST + r] = 0.0f;
    }
}

// Output layout (flattened, float32, reference return order):
//  O0 cls_kd_stu(4096) O1 cls_kd_tea(4096) O2 rois_tea(8*512*7)
//  O3 roi_scores_tea(4096) O4 roi_labels_tea(4096) O5 rois_stu(8*512*7)
//  O6 roi_scores_stu(4096) O7 roi_labels_stu(4096) O8 cls_select(8*512*3)
//  O9 select_mask(4096)
__global__ void k_gather(const float* __restrict__ box_tea,
                         const float* __restrict__ cls_tea,
                         const float* __restrict__ box_stu,
                         const float* __restrict__ cls_stu,
                         const float* __restrict__ cls_preds,
                         const float* __restrict__ rcnn,
                         float* __restrict__ out) {
    int t = blockIdx.x * blockDim.x + threadIdx.x;
    if (t >= BB * POST) return;
    const int O0 = 0, O1 = 4096, O2 = 8192, O3 = 36864, O4 = 40960;
    const int O5 = 45056, O6 = 73728, O7 = 77824, O8 = 81920, O9 = 94208;
    float m = g_msk[t];
    int idx = g_sel[t];
    int b = t / POST;
    size_t base = (size_t)b * NN + (size_t)idx;

    const float* ct = cls_tea + base * 3;
    float a0 = ct[0], a1 = ct[1], a2 = ct[2];
    float sT = a0;
    int lT = 0;
    if (a1 > sT) { sT = a1; lT = 1; }
    if (a2 > sT) { sT = a2; lT = 2; }

    const float* cs = cls_stu + base * 3;
    float b0 = cs[0], b1 = cs[1], b2 = cs[2];
    float sS = b0;
    int lS = 0;
    if (b1 > sS) { sS = b1; lS = 1; }
    if (b2 > sS) { sS = b2; lS = 2; }

    const float* pt = box_tea + base * 7;
    const float* ps = box_stu + base * 7;
    const float* pc = cls_preds + base * 3;
    float p0 = __fmul_rn(pc[0], m), p1 = __fmul_rn(pc[1], m), p2 = __fmul_rn(pc[2], m);

    out[O0 + t] = __fmul_rn(fmaxf(p0, fmaxf(p1, p2)), m);
    out[O1 + t] = __fmul_rn(rcnn[t], m);
#pragma unroll
    for (int j = 0; j < 7; j++) {
        out[O2 + t * 7 + j] = __fmul_rn(pt[j], m);
        out[O5 + t * 7 + j] = __fmul_rn(ps[j], m);
    }
    out[O3 + t] = __fmul_rn(sT, m);
    out[O4 + t] = (m > 0.0f) ? (float)(lT + 1) : 1.0f;
    out[O6 + t] = __fmul_rn(sS, m);
    out[O7 + t] = (m > 0.0f) ? (float)(lS + 1) : 1.0f;
    out[O8 + t * 3 + 0] = p0;
    out[O8 + t * 3 + 1] = p1;
    out[O8 + t * 3 + 2] = p2;
    out[O9 + t] = m;
}

extern "C" void kernel_launch(void* const* d_in, const int* in_sizes, int n_in,
                              void* d_out, int out_size) {
    const float* box_tea   = (const float*)d_in[0];
    const float* cls_tea   = (const float*)d_in[1];
    const float* box_stu   = (const float*)d_in[2];
    const float* cls_stu   = (const float*)d_in[3];
    const float* cls_preds = (const float*)d_in[4];
    const float* rcnn      = (const float*)d_in[5];
    float* out = (float*)d_out;

    k_zero<<<(BB * NBINS + 255) / 256, 256>>>();
    k_score<<<(BB * NN / 8) / 256, 256>>>((const float4*)cls_tea);
    k_compact<<<(BB * NN / 16) / 256, 256>>>();
    k_sort<<<BB, 1024>>>(box_tea);
    k_mask<<<dim3(32, 32, BB), 64>>>();
    k_scan<<<BB, 32>>>();
    k_gather<<<(BB * POST + 127) / 128, 128>>>(box_tea, cls_tea, box_stu, cls_stu,
                                               cls_preds, rcnn, out);
}

// round 13
// speedup vs baseline: 4.1143x; 1.3411x over previous
#include <cuda_runtime.h>

#define BB 8
#define NN 131072
#define PRE 2048
#define POST 512
#define CAP 4096
#define NBINS 256
#define SCORE_TH 0.1f
#define IOU_TH 0.7f
#define PD 32  // cp.async prefetch depth in k_scan (power of 2)

// ---------------- device scratch (no allocations allowed) ----------------
__device__ float              g_scores[BB * NN];
__device__ int                g_hist[BB * NBINS];
__device__ int                g_cutoff[BB];
__device__ int                g_cnt[BB];
__device__ int                g_ticket;
__device__ unsigned long long g_cand[BB * CAP];
__device__ int                g_topi[BB * PRE];
__device__ float              g_tops[BB * PRE];
__device__ int                g_sel[BB * POST];
__device__ float              g_msk[BB * POST];
__device__ float              g_gx1[BB * PRE], g_gx2[BB * PRE];
__device__ float              g_gy1[BB * PRE], g_gy2[BB * PRE];
__device__ float              g_gar[BB * PRE];
__device__ unsigned long long g_mask[BB * PRE * 32];

// ---------------- kernels ----------------
__global__ void k_zero() {
    int t = blockIdx.x * blockDim.x + threadIdx.x;
    if (t < BB * NBINS) g_hist[t] = 0;
    if (t < BB) g_cnt[t] = 0;
    if (t == 0) g_ticket = 0;
}

__device__ __forceinline__ int score_bin(float s) {
    int bin = (int)(s * (float)NBINS);
    return bin < 0 ? 0 : (bin > NBINS - 1 ? NBINS - 1 : bin);
}

// 8 boxes/thread (6x LDG.128). Block-local 256-bin smem histogram, one global
// flush per bin per block. Fused cutoff via last-block ticket.
__global__ void k_score(const float4* __restrict__ cls4) {
    __shared__ int hist[NBINS];
    int tid = threadIdx.x;  // 256 threads
    hist[tid] = 0;
    __syncthreads();
    int t = blockIdx.x * 256 + tid;  // grid = BB*NN/2048 = 512 blocks
    float4 q[6];
#pragma unroll
    for (int u = 0; u < 6; u++) q[u] = cls4[t * 6 + u];
    float s[8];
    s[0] = fmaxf(q[0].x, fmaxf(q[0].y, q[0].z));
    s[1] = fmaxf(q[0].w, fmaxf(q[1].x, q[1].y));
    s[2] = fmaxf(q[1].z, fmaxf(q[1].w, q[2].x));
    s[3] = fmaxf(q[2].y, fmaxf(q[2].z, q[2].w));
    s[4] = fmaxf(q[3].x, fmaxf(q[3].y, q[3].z));
    s[5] = fmaxf(q[3].w, fmaxf(q[4].x, q[4].y));
    s[6] = fmaxf(q[4].z, fmaxf(q[4].w, q[5].x));
    s[7] = fmaxf(q[5].y, fmaxf(q[5].z, q[5].w));
    float4* so = reinterpret_cast<float4*>(g_scores);
    so[t * 2 + 0] = make_float4(s[0], s[1], s[2], s[3]);
    so[t * 2 + 1] = make_float4(s[4], s[5], s[6], s[7]);
#pragma unroll
    for (int u = 0; u < 8; u++)
        if (s[u] >= SCORE_TH) atomicAdd(&hist[score_bin(s[u])], 1);
    __syncthreads();
    int b = blockIdx.x >> 6;  // 64 blocks per batch
    int v = hist[tid];
    if (v) atomicAdd(&g_hist[b * NBINS + tid], v);

    // ---- fused cutoff: last block computes all 8 batches ----
    __threadfence();
    __shared__ int isLast;
    if (tid == 0) isLast = (atomicAdd(&g_ticket, 1) == (int)gridDim.x - 1);
    __syncthreads();
    if (isLast) {
        int b2 = tid >> 5;
        int lane = tid & 31;
        int hi = NBINS - 8 * lane;  // lane covers 8 bins, lane 0 = topmost
        int lo = hi - 8;
        int sum = 0;
        for (int bin = lo; bin < hi; bin++) sum += g_hist[b2 * NBINS + bin];
        int incl = sum;
        for (int o = 1; o < 32; o <<= 1) {
            int n = __shfl_up_sync(0xffffffffu, incl, o);
            if (lane >= o) incl += n;
        }
        int excl = incl - sum;
        unsigned ball = __ballot_sync(0xffffffffu, incl >= PRE);
        if (ball) {
            int sel = __ffs(ball) - 1;
            if (lane == sel) {
                int acc = excl, bin;
                for (bin = hi - 1; bin >= lo; bin--) {
                    acc += g_hist[b2 * NBINS + bin];
                    if (acc >= PRE) break;
                }
                g_cutoff[b2] = bin;
            }
        } else if (lane == 0) {
            g_cutoff[b2] = 0;
        }
    }
}

// 16 scores/thread; warp-aggregated g_cnt atomic (1 per warp, not 1 per item).
__global__ void k_compact() {
    int t = blockIdx.x * blockDim.x + threadIdx.x;  // BB*NN/16 threads
    const float4* sp = reinterpret_cast<const float4*>(g_scores);
    float4 f[4];
#pragma unroll
    for (int u = 0; u < 4; u++) f[u] = sp[t * 4 + u];
    float s[16];
#pragma unroll
    for (int u = 0; u < 4; u++) {
        s[u * 4 + 0] = f[u].x;
        s[u * 4 + 1] = f[u].y;
        s[u * 4 + 2] = f[u].z;
        s[u * 4 + 3] = f[u].w;
    }
    int b = t >> 13;  // 16t/NN; whole warp is same batch (512 boxes/warp)
    int cut = g_cutoff[b];
    int lane = threadIdx.x & 31;
    int c = 0;
#pragma unroll
    for (int u = 0; u < 16; u++)
        if (s[u] >= SCORE_TH && score_bin(s[u]) >= cut) c++;
    int incl = c;
    for (int o = 1; o < 32; o <<= 1) {
        int n = __shfl_up_sync(0xffffffffu, incl, o);
        if (lane >= o) incl += n;
    }
    int total = __shfl_sync(0xffffffffu, incl, 31);
    int base = 0;
    if (lane == 31 && total > 0) base = atomicAdd(&g_cnt[b], total);
    base = __shfl_sync(0xffffffffu, base, 31);
    int pos = base + (incl - c);
    int gi = t * 16;
#pragma unroll
    for (int u = 0; u < 16; u++) {
        if (s[u] >= SCORE_TH && score_bin(s[u]) >= cut) {
            if (pos < CAP) {
                // score bits high; ~local_index low -> lower index wins ties
                unsigned lo = ~(unsigned)((gi + u) & (NN - 1));
                g_cand[b * CAP + pos] =
                    ((unsigned long long)__float_as_uint(s[u]) << 32) |
                    (unsigned long long)lo;
            }
            pos++;
        }
    }
}

// Sort phase A: 2 CTAs per batch; CTA h sorts its 2048-chunk. dir computed
// from the GLOBAL element index ig = h*2048 + i, which makes phases A+B
// bit-identical to the proven monolithic 4096 bitonic network (chunk 0 ends
// descending, chunk 1 ascending after the k=2048 stage).
__global__ void k_sortA() {
    __shared__ unsigned long long sh[2048];
    int h = blockIdx.x, b = blockIdx.y;
    int t = threadIdx.x;  // 1024 threads, 2 elems each
    int cnt = g_cnt[b];
    if (cnt > CAP) cnt = CAP;
    unsigned long long v[2];
#pragma unroll
    for (int s = 0; s < 2; s++) {
        int g = h * 2048 + 2 * t + s;
        v[s] = (g < cnt) ? g_cand[b * CAP + g] : 0ULL;
    }
    for (int k = 2; k <= 2048; k <<= 1) {
        for (int j = k >> 1; j >= 64; j >>= 1) {  // smem passes
            sh[2 * t + 0] = v[0];
            sh[2 * t + 1] = v[1];
            __syncthreads();
#pragma unroll
            for (int s = 0; s < 2; s++) {
                int i = 2 * t + s;
                int ig = h * 2048 + i;
                unsigned long long p = sh[i ^ j];
                bool dir = ((ig & k) == 0);
                bool low = ((i & j) == 0);
                bool keepMax = (dir == low);
                unsigned long long mx = v[s] > p ? v[s] : p;
                unsigned long long mn = v[s] > p ? p : v[s];
                v[s] = keepMax ? mx : mn;
            }
            __syncthreads();
        }
        int jhi = (k >> 1) < 32 ? (k >> 1) : 32;
        for (int j = jhi; j >= 2; j >>= 1) {  // shfl passes (partner t^(j/2))
            int jt = j >> 1;
#pragma unroll
            for (int s = 0; s < 2; s++) {
                unsigned long long p = __shfl_xor_sync(0xffffffffu, v[s], jt);
                int ig = h * 2048 + 2 * t + s;
                bool dir = ((ig & k) == 0);
                bool low = ((t & jt) == 0);
                bool keepMax = (dir == low);
                unsigned long long mx = v[s] > p ? v[s] : p;
                unsigned long long mn = v[s] > p ? p : v[s];
                v[s] = keepMax ? mx : mn;
            }
        }
        {  // j=1 reg pass (pair within thread)
            int ig = h * 2048 + 2 * t;
            bool dir = ((ig & k) == 0);
            unsigned long long a = v[0], c2 = v[1];
            bool sw = dir ? (a < c2) : (a > c2);
            if (sw) { v[0] = c2; v[1] = a; }
        }
    }
#pragma unroll
    for (int s = 0; s < 2; s++) g_cand[b * CAP + h * 2048 + 2 * t + s] = v[s];
}

// Sort phase B: final k=4096 merge (input bitonic: desc-chunk then asc-chunk);
// dir = true for all i (i & 4096 == 0). Then emit tops/topi + geometry SoA.
__global__ void k_sortB(const float* __restrict__ boxes_tea) {
    __shared__ unsigned long long sh[CAP];
    int b = blockIdx.x;
    int t = threadIdx.x;  // 1024 threads, 4 elems each
    unsigned long long v[4];
#pragma unroll
    for (int s = 0; s < 4; s++) v[s] = g_cand[b * CAP + 4 * t + s];
    for (int j = 2048; j >= 128; j >>= 1) {  // smem passes
#pragma unroll
        for (int s = 0; s < 4; s++) sh[4 * t + s] = v[s];
        __syncthreads();
#pragma unroll
        for (int s = 0; s < 4; s++) {
            int i = 4 * t + s;
            unsigned long long p = sh[i ^ j];
            bool low = ((i & j) == 0);  // dir = true
            unsigned long long mx = v[s] > p ? v[s] : p;
            unsigned long long mn = v[s] > p ? p : v[s];
            v[s] = low ? mx : mn;
        }
        __syncthreads();
    }
    for (int j = 64; j >= 4; j >>= 1) {  // shfl passes
        int jt = j >> 2;
#pragma unroll
        for (int s = 0; s < 4; s++) {
            unsigned long long p = __shfl_xor_sync(0xffffffffu, v[s], jt);
            bool low = ((t & jt) == 0);
            unsigned long long mx = v[s] > p ? v[s] : p;
            unsigned long long mn = v[s] > p ? p : v[s];
            v[s] = low ? mx : mn;
        }
    }
#pragma unroll
    for (int s = 0; s < 2; s++) {  // j=2
        unsigned long long a = v[s], c2 = v[s + 2];
        if (a < c2) { v[s] = c2; v[s + 2] = a; }
    }
#pragma unroll
    for (int s = 0; s < 4; s += 2) {  // j=1
        unsigned long long a = v[s], c2 = v[s + 1];
        if (a < c2) { v[s] = c2; v[s + 1] = a; }
    }
#pragma unroll
    for (int s = 0; s < 4; s++) sh[4 * t + s] = v[s];
    __syncthreads();
    for (int r = t; r < PRE; r += 1024) {
        unsigned long long key = sh[r];
        float sc = __uint_as_float((unsigned)(key >> 32));
        int idx = (int)(~(unsigned)key);
        if (sc < SCORE_TH) idx = 0;  // padding: never kept, safe index
        g_tops[b * PRE + r] = sc;
        g_topi[b * PRE + r] = idx;
        const float* bp = boxes_tea + ((size_t)b * NN + idx) * 7;
        float x = bp[0], y = bp[1], dx = bp[3], dy = bp[4];
        float hx = __fmul_rn(0.5f, dx), hy = __fmul_rn(0.5f, dy);
        int g = b * PRE + r;
        g_gx1[g] = __fsub_rn(x, hx);
        g_gx2[g] = __fadd_rn(x, hx);
        g_gy1[g] = __fsub_rn(y, hy);
        g_gy2[g] = __fadd_rn(y, hy);
        g_gar[g] = __fmul_rn(dx, dy);
    }
}

// Suppression bit matrix, chip-parallel. Lower-triangle words never read.
__global__ void k_mask() {
    __shared__ float cx1[64], cx2[64], cy1[64], cy2[64], car[64];
    int bx = blockIdx.x, by = blockIdx.y, b = blockIdx.z;
    if (bx < by) return;
    int tid = threadIdx.x;
    int i = by * 64 + tid;
    int base = b * PRE;
    int c = bx * 64 + tid;
    cx1[tid] = g_gx1[base + c];
    cx2[tid] = g_gx2[base + c];
    cy1[tid] = g_gy1[base + c];
    cy2[tid] = g_gy2[base + c];
    car[tid] = g_gar[base + c];
    __syncthreads();
    float x1 = g_gx1[base + i], x2 = g_gx2[base + i];
    float y1 = g_gy1[base + i], y2 = g_gy2[base + i];
    float ar = g_gar[base + i];
    unsigned long long word = 0ULL;
#pragma unroll 16
    for (int k = 0; k < 64; k++) {
        int j = bx * 64 + k;
        float iw = fmaxf(__fsub_rn(fminf(x2, cx2[k]), fmaxf(x1, cx1[k])), 0.0f);
        float ih = fmaxf(__fsub_rn(fminf(y2, cy2[k]), fmaxf(y1, cy1[k])), 0.0f);
        float inter = __fmul_rn(iw, ih);
        float denom = fmaxf(__fsub_rn(__fadd_rn(ar, car[k]), inter), 1e-6f);
        float iou = __fdiv_rn(inter, denom);
        if ((j > i) && (iou > IOU_TH)) word |= (1ULL << k);
    }
    g_mask[(size_t)(base + i) * 32 + bx] = word;
}

__device__ __forceinline__ void cp_async8(void* smem_dst, const void* gmem_src) {
    unsigned d = (unsigned)__cvta_generic_to_shared(smem_dst);
    asm volatile("cp.async.ca.shared.global [%0], [%1], 8;" ::"r"(d), "l"(gmem_src));
}
__device__ __forceinline__ void cp_commit() { asm volatile("cp.async.commit_group;"); }
__device__ __forceinline__ void cp_wait_back() { asm volatile("cp.async.wait_group 31;"); }
__device__ __forceinline__ void cp_wait_all() { asm volatile("cp.async.wait_group 0;"); }

// Serial greedy scan: 1 warp/batch; lane owns one u64 of the 2048-bit
// accumulator; PD=32 prefetch ring fully hides L2 latency.
__global__ void k_scan() {
    __shared__ unsigned long long ring[PD][32];
    int b = blockIdx.x;
    int lane = threadIdx.x;
    const unsigned long long* rowbase = g_mask + (size_t)b * PRE * 32;

    unsigned long long acc = 0ULL;  // pre-seed invalid rows
    for (int k = 0; k < 64; k++) {
        float s = g_tops[b * PRE + lane * 64 + k];
        if (s < SCORE_TH) acc |= (1ULL << k);
    }
    for (int p = 0; p < PD; p++) {
        cp_async8(&ring[p][lane], rowbase + (size_t)p * 32 + lane);
        cp_commit();
    }
    int cnt = 0;
    for (int i = 0; i < PRE; i++) {
        cp_wait_back();
        unsigned long long w = __shfl_sync(0xffffffffu, acc, i >> 6);
        bool keep = !((w >> (i & 63)) & 1ULL);
        int slot = i & (PD - 1);
        if (keep) {
            if (lane == 0) {
                g_sel[b * POST + cnt] = g_topi[b * PRE + i];
                g_msk[b * POST + cnt] = 1.0f;
            }
            if (lane >= (i >> 6)) acc |= ring[slot][lane];
            cnt++;
            if (cnt >= POST) break;
        }
        int nr = i + PD;
        if (nr > PRE - 1) nr = PRE - 1;
        cp_async8(&ring[slot][lane], rowbase + (size_t)nr * 32 + lane);
        cp_commit();
    }
    cp_wait_all();
    for (int r = cnt + lane; r < POST; r += 32) {
        g_sel[b * POST + r] = 0;
        g_msk[b * POST + r] = 0.0f;
    }
}

// Output layout (flattened, float32, reference return order):
//  O0 cls_kd_stu(4096) O1 cls_kd_tea(4096) O2 rois_tea(8*512*7)
//  O3 roi_scores_tea(4096) O4 roi_labels_tea(4096) O5 rois_stu(8*512*7)
//  O6 roi_scores_stu(4096) O7 roi_labels_stu(4096) O8 cls_select(8*512*3)
//  O9 select_mask(4096)
__global__ void k_gather(const float* __restrict__ box_tea,
                         const float* __restrict__ cls_tea,
                         const float* __restrict__ box_stu,
                         const float* __restrict__ cls_stu,
                         const float* __restrict__ cls_preds,
                         const float* __restrict__ rcnn,
                         float* __restrict__ out) {
    int t = blockIdx.x * blockDim.x + threadIdx.x;
    if (t >= BB * POST) return;
    const int O0 = 0, O1 = 4096, O2 = 8192, O3 = 36864, O4 = 40960;
    const int O5 = 45056, O6 = 73728, O7 = 77824, O8 = 81920, O9 = 94208;
    float m = g_msk[t];
    int idx = g_sel[t];
    int b = t / POST;
    size_t base = (size_t)b * NN + (size_t)idx;

    const float* ct = cls_tea + base * 3;
    float a0 = ct[0], a1 = ct[1], a2 = ct[2];
    float sT = a0;
    int lT = 0;
    if (a1 > sT) { sT = a1; lT = 1; }
    if (a2 > sT) { sT = a2; lT = 2; }

    const float* cs = cls_stu + base * 3;
    float b0 = cs[0], b1 = cs[1], b2 = cs[2];
    float sS = b0;
    int lS = 0;
    if (b1 > sS) { sS = b1; lS = 1; }
    if (b2 > sS) { sS = b2; lS = 2; }

    const float* pt = box_tea + base * 7;
    const float* ps = box_stu + base * 7;
    const float* pc = cls_preds + base * 3;
    float p0 = __fmul_rn(pc[0], m), p1 = __fmul_rn(pc[1], m), p2 = __fmul_rn(pc[2], m);

    out[O0 + t] = __fmul_rn(fmaxf(p0, fmaxf(p1, p2)), m);
    out[O1 + t] = __fmul_rn(rcnn[t], m);
#pragma unroll
    for (int j = 0; j < 7; j++) {
        out[O2 + t * 7 + j] = __fmul_rn(pt[j], m);
        out[O5 + t * 7 + j] = __fmul_rn(ps[j], m);
    }
    out[O3 + t] = __fmul_rn(sT, m);
    out[O4 + t] = (m > 0.0f) ? (float)(lT + 1) : 1.0f;
    out[O6 + t] = __fmul_rn(sS, m);
    out[O7 + t] = (m > 0.0f) ? (float)(lS + 1) : 1.0f;
    out[O8 + t * 3 + 0] = p0;
    out[O8 + t * 3 + 1] = p1;
    out[O8 + t * 3 + 2] = p2;
    out[O9 + t] = m;
}

extern "C" void kernel_launch(void* const* d_in, const int* in_sizes, int n_in,
                              void* d_out, int out_size) {
    const float* box_tea   = (const float*)d_in[0];
    const float* cls_tea   = (const float*)d_in[1];
    const float* box_stu   = (const float*)d_in[2];
    const float* cls_stu   = (const float*)d_in[3];
    const float* cls_preds = (const float*)d_in[4];
    const float* rcnn      = (const float*)d_in[5];
    float* out = (float*)d_out;

    k_zero<<<8, 256>>>();
    k_score<<<BB * NN / 2048, 256>>>((const float4*)cls_tea);
    k_compact<<<(BB * NN / 16) / 256, 256>>>();
    k_sortA<<<dim3(2, BB), 1024>>>();
    k_sortB<<<BB, 1024>>>(box_tea);
    k_mask<<<dim3(32, 32, BB), 64>>>();
    k_scan<<<BB, 32>>>();
    k_gather<<<(BB * POST + 127) / 128, 128>>>(box_tea, cls_tea, box_stu, cls_stu,
                                               cls_preds, rcnn, out);
}